// round 1
// baseline (speedup 1.0000x reference)
#include <cuda_runtime.h>
#include <math.h>

// Problem constants (fixed by the dataset)
#define NN   1024            // nodes
#define BB   8               // batch
#define HH   64              // hidden
#define TT   128             // time steps
#define FF   1               // features
#define CIN  66              // 2*F + H
#define M0   (BB*CIN)        // 528 rows for xh diffusion
#define MH   (BB*HH)         // 512 rows for r*h diffusion / states
#define KTOT 330             // 5*CIN concat channels

// ---------------- scratch (device globals; no allocation allowed) -------------
__device__ float g_AfT[NN*NN];
__device__ float g_AbT[NN*NN];
__device__ float g_Z0 [M0*NN];
__device__ float g_Z1f[M0*NN];
__device__ float g_Z2f[M0*NN];
__device__ float g_Z1b[M0*NN];
__device__ float g_Z2b[M0*NN];
__device__ float g_RH [MH*NN];
__device__ float g_R1f[MH*NN];
__device__ float g_R2f[MH*NN];
__device__ float g_R1b[MH*NN];
__device__ float g_R2b[MH*NN];
__device__ float g_U  [MH*NN];
__device__ float g_rowinv[NN];
__device__ float g_colinv[NN];
__device__ int   g_nz[4];
__device__ int   g_maskmode;
__device__ float g_states[(size_t)TT*MH*NN];   // [t][(b*H+h)*N+n], 268MB

// ---------------- helpers -----------------------------------------------------
__device__ __forceinline__ const float* zc_src(int blk) {
    switch (blk) {
        case 0:  return g_Z0;
        case 1:  return g_Z1f;
        case 2:  return g_Z2f;
        case 3:  return g_Z1b;
        default: return g_Z2b;
    }
}
__device__ __forceinline__ const float* rc_src(int blk) {
    switch (blk) {
        case 0:  return g_RH;
        case 1:  return g_R1f;
        case 2:  return g_R2f;
        case 3:  return g_R1b;
        default: return g_R2b;
    }
}

// ---------------- prologue ----------------------------------------------------
__global__ void zero_init() {
    int idx = blockIdx.x * blockDim.x + threadIdx.x;
    if (idx < 4) g_nz[idx] = 0;
    for (int i = idx; i < MH*NN; i += gridDim.x * blockDim.x) {
        int n  = i & (NN-1);
        int r  = i >> 10;
        int hh = r & (HH-1);
        int b  = r >> 6;
        g_Z0[(b*CIN + 2 + hh)*NN + n] = 0.f;   // h0 = 0
    }
}

// Detect mask storage layout: scan first BB*NN*TT bytes (safe for u8/i32/f32).
__global__ void mask_detect(const unsigned char* __restrict__ p) {
    int f0 = 0, f1 = 0, f2 = 0, f3 = 0;
    for (int i = blockIdx.x*blockDim.x + threadIdx.x; i < BB*NN*TT;
         i += gridDim.x * blockDim.x) {
        if (p[i]) {
            int c = i & 3;
            if (c == 0) f0 = 1; else if (c == 1) f1 = 1;
            else if (c == 2) f2 = 1; else f3 = 1;
        }
    }
    unsigned b0 = __ballot_sync(0xffffffffu, f0);
    unsigned b1 = __ballot_sync(0xffffffffu, f1);
    unsigned b2 = __ballot_sync(0xffffffffu, f2);
    unsigned b3 = __ballot_sync(0xffffffffu, f3);
    if ((threadIdx.x & 31) == 0) {
        if (b0) atomicOr(&g_nz[0], 1);
        if (b1) atomicOr(&g_nz[1], 1);
        if (b2) atomicOr(&g_nz[2], 1);
        if (b3) atomicOr(&g_nz[3], 1);
    }
}

__global__ void mask_finalize() {
    // i32 0/1: only byte-class 0 nonzero.  u8 0/1: all classes nonzero.
    // f32 0.0/1.0: classes 2,3 nonzero, class 0 zero.
    if ((g_nz[1] | g_nz[2] | g_nz[3]) == 0) g_maskmode = 0;       // int32
    else g_maskmode = g_nz[0] ? 1 : 2;                            // u8 : f32
}

__global__ void rowsum_k(const float* __restrict__ adj) {
    int w = blockIdx.x;
    float s = 0.f;
    for (int v = threadIdx.x; v < NN; v += blockDim.x) s += adj[w*NN + v];
    __shared__ float red[256];
    red[threadIdx.x] = s;
    __syncthreads();
    for (int off = 128; off > 0; off >>= 1) {
        if (threadIdx.x < off) red[threadIdx.x] += red[threadIdx.x + off];
        __syncthreads();
    }
    if (threadIdx.x == 0) g_rowinv[w] = 1.f / (red[0] + 1e-8f);
}

__global__ void colsum_k(const float* __restrict__ adj) {
    int w = blockIdx.x * blockDim.x + threadIdx.x;
    if (w >= NN) return;
    float s = 0.f;
    for (int v = 0; v < NN; v++) s += adj[v*NN + w];
    g_colinv[w] = 1.f / (s + 1e-8f);
}

// AfT[v][w] = adj[w][v] / rowsum[w];  AbT[v][w] = adj[v][w] / colsum[w]
__global__ void buildA(const float* __restrict__ adj) {
    for (int i = blockIdx.x*blockDim.x + threadIdx.x; i < NN*NN;
         i += gridDim.x * blockDim.x) {
        int w = i & (NN-1);
        int v = i >> 10;
        g_AfT[i] = adj[w*NN + v] * g_rowinv[w];
        g_AbT[i] = adj[i]        * g_colinv[w];
    }
}

// ---------------- per-step elementwise: x_hat, outputs, build Z0 inp rows -----
__global__ void phaseA(const float* __restrict__ x, const void* __restrict__ mask,
                       const float* __restrict__ Wout, const float* __restrict__ bout,
                       float* __restrict__ preds, int t) {
    int idx = blockIdx.x * blockDim.x + threadIdx.x;
    if (idx >= MH*NN) return;
    int n  = idx & (NN-1);
    int r  = idx >> 10;
    int hh = r & (HH-1);
    int b  = r >> 6;
    float h = g_Z0[(b*CIN + 2 + hh)*NN + n];
    g_states[(size_t)t*(MH*NN) + idx] = h;          // state at entry of step t
    if (hh == 0) {
        float acc = 0.f;
        #pragma unroll
        for (int k = 0; k < HH; k++)
            acc += Wout[k] * g_Z0[(b*CIN + 2 + k)*NN + n];
        float xh = acc + bout[0];
        int mi = (b*NN + n)*TT + t;
        preds[mi] = xh;
        int mm = g_maskmode;
        float mval;
        if (mm == 0)      mval = ((const int*)mask)[mi]            ? 1.f : 0.f;
        else if (mm == 1) mval = ((const unsigned char*)mask)[mi]  ? 1.f : 0.f;
        else              mval = (((const float*)mask)[mi] != 0.f) ? 1.f : 0.f;
        float xin = (mval != 0.f) ? x[mi] : xh;
        g_Z0[(b*CIN + 0)*NN + n] = xin;
        g_Z0[(b*CIN + 1)*NN + n] = mval;
    }
}

// ---------------- diffusion SGEMM: D = S(MxK) * A(KxN), K=N=1024 --------------
// phase 0: Z0  -> Z1{f,b}  (M=528)     phase 1: Z1 -> Z2 (M=528)
// phase 2: RH  -> R1{f,b}  (M=512)     phase 3: R1 -> R2 (M=512)
// blockIdx.z = 0 forward support, 1 backward support.
__global__ void __launch_bounds__(256)
gemm_nn(int phase) {
    const float* S; float* D; int M;
    const int zz = blockIdx.z;
    switch (phase) {
        case 0: S = g_Z0;                   D = zz ? g_Z1b : g_Z1f; M = M0; break;
        case 1: S = zz ? g_Z1b : g_Z1f;     D = zz ? g_Z2b : g_Z2f; M = M0; break;
        case 2: S = g_RH;                   D = zz ? g_R1b : g_R1f; M = MH; break;
        default:S = zz ? g_R1b : g_R1f;     D = zz ? g_R2b : g_R2f; M = MH; break;
    }
    const float* Amat = zz ? g_AbT : g_AfT;

    const int m0 = blockIdx.y * 64;
    const int n0 = blockIdx.x * 64;

    __shared__ float As[2][16][68];
    __shared__ float Bs[2][16][68];

    const int t  = threadIdx.x;
    const int am = t >> 2;              // 0..63, row of A tile
    const int ak = (t & 3) << 2;        // 0,4,8,12 k-quad
    const int bk = t >> 4;              // 0..15
    const int bn = (t & 15) << 2;       // n-quad
    const int ty = t >> 4;              // micro-tile row group
    const int tx = t & 15;              // micro-tile col group

    const bool avalid = (m0 + am) < M;
    const float* Aptr = S + (size_t)(m0 + am)*NN + ak;
    const float* Bptr = Amat + (size_t)bk*NN + n0 + bn;

    float acc[4][4] = {};

    float4 ra = avalid ? *(const float4*)Aptr : make_float4(0.f,0.f,0.f,0.f);
    float4 rb = *(const float4*)Bptr;
    int buf = 0;
    As[0][ak+0][am] = ra.x; As[0][ak+1][am] = ra.y;
    As[0][ak+2][am] = ra.z; As[0][ak+3][am] = ra.w;
    *(float4*)&Bs[0][bk][bn] = rb;
    __syncthreads();

    #pragma unroll 1
    for (int kc = 0; kc < 64; kc++) {
        if (kc < 63) {
            ra = avalid ? *(const float4*)(Aptr + (kc+1)*16)
                        : make_float4(0.f,0.f,0.f,0.f);
            rb = *(const float4*)(Bptr + (size_t)(kc+1)*16*NN);
        }
        #pragma unroll
        for (int k = 0; k < 16; k++) {
            const float4 av = *(const float4*)&As[buf][k][ty << 2];
            const float4 bv = *(const float4*)&Bs[buf][k][tx << 2];
            acc[0][0] += av.x*bv.x; acc[0][1] += av.x*bv.y;
            acc[0][2] += av.x*bv.z; acc[0][3] += av.x*bv.w;
            acc[1][0] += av.y*bv.x; acc[1][1] += av.y*bv.y;
            acc[1][2] += av.y*bv.z; acc[1][3] += av.y*bv.w;
            acc[2][0] += av.z*bv.x; acc[2][1] += av.z*bv.y;
            acc[2][2] += av.z*bv.z; acc[2][3] += av.z*bv.w;
            acc[3][0] += av.w*bv.x; acc[3][1] += av.w*bv.y;
            acc[3][2] += av.w*bv.z; acc[3][3] += av.w*bv.w;
        }
        if (kc < 63) {
            const int nb = buf ^ 1;
            As[nb][ak+0][am] = ra.x; As[nb][ak+1][am] = ra.y;
            As[nb][ak+2][am] = ra.z; As[nb][ak+3][am] = ra.w;
            *(float4*)&Bs[nb][bk][bn] = rb;
            __syncthreads();
            buf = nb;
        }
    }

    #pragma unroll
    for (int i = 0; i < 4; i++) {
        int m = m0 + (ty << 2) + i;
        if (m < M) {
            float4 v = make_float4(acc[i][0], acc[i][1], acc[i][2], acc[i][3]);
            *(float4*)(D + (size_t)m*NN + n0 + (tx << 2)) = v;
        }
    }
}

// ---------------- r/u gate projections (K=330) --------------------------------
// grid (16, 8): n-tile of 64 per batch b. 128 outputs (r:0..63, u:64..127).
__global__ void __launch_bounds__(256)
gates_ru(const float* __restrict__ Wr, const float* __restrict__ br,
         const float* __restrict__ Wu, const float* __restrict__ bu) {
    const int b  = blockIdx.y;
    const int n0 = blockIdx.x * 64;
    __shared__ float Ws[8][128];
    __shared__ float Zs[8][64];
    const int t  = threadIdx.x;
    const int ty = t >> 4;        // o-group: 8 outputs
    const int tx = t & 15;        // n-group: 4 cols
    float acc[8][4] = {};

    for (int c0 = 0; c0 < KTOT; c0 += 8) {
        #pragma unroll
        for (int i = 0; i < 4; i++) {
            int idx = t + i*256;
            int kk = idx >> 7, o = idx & 127;
            int c = c0 + kk;
            float w = 0.f;
            if (c < KTOT) w = (o < 64) ? Wr[o*KTOT + c] : Wu[(o-64)*KTOT + c];
            Ws[kk][o] = w;
        }
        #pragma unroll
        for (int i = 0; i < 2; i++) {
            int idx = t + i*256;
            int kk = idx >> 6, nn2 = idx & 63;
            int c = c0 + kk;
            float z = 0.f;
            if (c < KTOT) {
                int blk = c / 66, cc = c - blk*66;
                z = zc_src(blk)[(b*CIN + cc)*NN + n0 + nn2];
            }
            Zs[kk][nn2] = z;
        }
        __syncthreads();
        #pragma unroll
        for (int kk = 0; kk < 8; kk++) {
            float4 w0 = *(const float4*)&Ws[kk][ty*8];
            float4 w1 = *(const float4*)&Ws[kk][ty*8 + 4];
            float4 zz = *(const float4*)&Zs[kk][tx*4];
            float wv[8] = {w0.x,w0.y,w0.z,w0.w,w1.x,w1.y,w1.z,w1.w};
            float zv[4] = {zz.x,zz.y,zz.z,zz.w};
            #pragma unroll
            for (int i = 0; i < 8; i++)
                #pragma unroll
                for (int j = 0; j < 4; j++)
                    acc[i][j] += wv[i]*zv[j];
        }
        __syncthreads();
    }

    #pragma unroll
    for (int i = 0; i < 8; i++) {
        int o = ty*8 + i;
        float bias = (o < 64) ? br[o] : bu[o-64];
        #pragma unroll
        for (int j = 0; j < 4; j++) {
            int n = n0 + tx*4 + j;
            float p = acc[i][j] + bias;
            float s = 1.f / (1.f + expf(-p));
            if (o < 64)
                g_RH[(b*HH + o)*NN + n] = s * g_Z0[(b*CIN + 2 + o)*NN + n];
            else
                g_U[(b*HH + (o-64))*NN + n] = s;
        }
    }
}

// ---------------- c gate + h update -------------------------------------------
__global__ void __launch_bounds__(256)
gate_c(const float* __restrict__ Wc, const float* __restrict__ bc) {
    const int b  = blockIdx.y;
    const int n0 = blockIdx.x * 64;
    __shared__ float Ws[8][64];
    __shared__ float Zs[8][64];
    const int t  = threadIdx.x;
    const int ty = t >> 4;
    const int tx = t & 15;
    float acc[4][4] = {};

    for (int c0 = 0; c0 < KTOT; c0 += 8) {
        #pragma unroll
        for (int i = 0; i < 2; i++) {
            int idx = t + i*256;
            int kk = idx >> 6, o = idx & 63;
            int c = c0 + kk;
            Ws[kk][o] = (c < KTOT) ? Wc[o*KTOT + c] : 0.f;
        }
        #pragma unroll
        for (int i = 0; i < 2; i++) {
            int idx = t + i*256;
            int kk = idx >> 6, nn2 = idx & 63;
            int c = c0 + kk;
            float z = 0.f;
            if (c < KTOT) {
                int blk = c / 66, cc = c - blk*66;
                if (cc < 2) z = zc_src(blk)[(b*CIN + cc)*NN + n0 + nn2];
                else        z = rc_src(blk)[(b*HH + cc - 2)*NN + n0 + nn2];
            }
            Zs[kk][nn2] = z;
        }
        __syncthreads();
        #pragma unroll
        for (int kk = 0; kk < 8; kk++) {
            float4 w4 = *(const float4*)&Ws[kk][ty*4];
            float4 z4 = *(const float4*)&Zs[kk][tx*4];
            float wv[4] = {w4.x,w4.y,w4.z,w4.w};
            float zv[4] = {z4.x,z4.y,z4.z,z4.w};
            #pragma unroll
            for (int i = 0; i < 4; i++)
                #pragma unroll
                for (int j = 0; j < 4; j++)
                    acc[i][j] += wv[i]*zv[j];
        }
        __syncthreads();
    }

    #pragma unroll
    for (int i = 0; i < 4; i++) {
        int o = ty*4 + i;
        float bias = bc[o];
        #pragma unroll
        for (int j = 0; j < 4; j++) {
            int n = n0 + tx*4 + j;
            float cv = tanhf(acc[i][j] + bias);
            float hold = g_Z0[(b*CIN + 2 + o)*NN + n];
            float u    = g_U[(b*HH + o)*NN + n];
            g_Z0[(b*CIN + 2 + o)*NN + n] = u*hold + (1.f - u)*cv;
        }
    }
}

// ---------------- epilogue: states transpose [T][M] -> [M][T] -----------------
__global__ void transpose_states(float* __restrict__ dst) {
    __shared__ float tile[32][33];
    const int m0 = blockIdx.x * 32;
    const int t0 = blockIdx.y * 32;
    const int tx = threadIdx.x;   // 0..31
    const int ty = threadIdx.y;   // 0..7
    #pragma unroll
    for (int j = 0; j < 4; j++) {
        int tt = t0 + ty + j*8;
        tile[ty + j*8][tx] = g_states[(size_t)tt*(MH*NN) + m0 + tx];
    }
    __syncthreads();
    #pragma unroll
    for (int j = 0; j < 4; j++) {
        int mm = m0 + ty + j*8;
        dst[(size_t)mm*TT + t0 + tx] = tile[tx][ty + j*8];
    }
}

// ---------------- host driver -------------------------------------------------
extern "C" void kernel_launch(void* const* d_in, const int* in_sizes, int n_in,
                              void* d_out, int out_size) {
    const float* x    = (const float*)d_in[0];
    const void*  mask = d_in[1];
    const float* adj  = (const float*)d_in[2];
    const float* Wr   = (const float*)d_in[3];
    const float* br   = (const float*)d_in[4];
    const float* Wu   = (const float*)d_in[5];
    const float* bu   = (const float*)d_in[6];
    const float* Wc   = (const float*)d_in[7];
    const float* bc   = (const float*)d_in[8];
    const float* Wout = (const float*)d_in[9];
    const float* bout = (const float*)d_in[10];

    float* preds  = (float*)d_out;                 // [B,F,N,T] = 1,048,576
    float* states = preds + (size_t)BB*NN*TT;      // [1,B,H,N,T] follows

    zero_init<<<512, 256>>>();
    mask_detect<<<64, 256>>>((const unsigned char*)mask);
    mask_finalize<<<1, 1>>>();
    rowsum_k<<<NN, 256>>>(adj);
    colsum_k<<<NN/256, 256>>>(adj);
    buildA<<<2048, 256>>>(adj);

    dim3 gBC(16, (M0 + 63)/64, 2);   // 16 x 9 x 2
    dim3 gEF(16, MH/64, 2);          // 16 x 8 x 2
    dim3 gGate(16, BB);

    for (int t = 0; t < TT; t++) {
        phaseA<<<(MH*NN)/256, 256>>>(x, mask, Wout, bout, preds, t);
        gemm_nn<<<gBC, 256>>>(0);            // Z0 -> Z1f/Z1b
        gemm_nn<<<gBC, 256>>>(1);            // Z1 -> Z2f/Z2b
        gates_ru<<<gGate, 256>>>(Wr, br, Wu, bu);
        gemm_nn<<<gEF, 256>>>(2);            // RH -> R1f/R1b
        gemm_nn<<<gEF, 256>>>(3);            // R1 -> R2f/R2b
        gate_c<<<gGate, 256>>>(Wc, bc);
    }

    transpose_states<<<dim3((MH*NN)/32, TT/32), dim3(32, 8)>>>(states);
}

// round 5
// speedup vs baseline: 1.4815x; 1.4815x over previous
#include <cuda_runtime.h>
#include <cuda_fp16.h>
#include <math.h>
#include <stdint.h>

// Problem constants
#define NN   1024
#define BB   8
#define HH   64
#define TT   128
#define CIN  66              // 2*F + H
#define M0   (BB*CIN)        // 528
#define MH   (BB*HH)         // 512
#define MPAD 640             // 528 padded to 5*128
#define KTOT 330

// ---------------- scratch ----------------
__device__ float  g_Bf [NN*NN];
__device__ float  g_Bb [NN*NN];
__device__ float  g_Bf2[NN*NN];
__device__ float  g_Bb2[NN*NN];
__device__ __align__(16) __half g_Bcat_hi[4*NN*NN];
__device__ __align__(16) __half g_Bcat_lo[4*NN*NN];

__device__ float  g_Z0 [M0*NN];
__device__ __align__(16) __half g_Z0hi[MPAD*NN];
__device__ __align__(16) __half g_Z0lo[MPAD*NN];
__device__ float  g_Z1f[MPAD*NN];
__device__ float  g_Z2f[MPAD*NN];
__device__ float  g_Z1b[MPAD*NN];
__device__ float  g_Z2b[MPAD*NN];

__device__ float  g_RH [MH*NN];
__device__ __align__(16) __half g_RHhi[MH*NN];
__device__ __align__(16) __half g_RHlo[MH*NN];
__device__ float  g_R1f[MH*NN];
__device__ float  g_R2f[MH*NN];
__device__ float  g_R1b[MH*NN];
__device__ float  g_R2b[MH*NN];
__device__ float  g_U  [MH*NN];

__device__ float  g_rowinv[NN];
__device__ float  g_colinv[NN];
__device__ int    g_nz[4];
__device__ int    g_maskmode;
__device__ float  g_states[(size_t)TT*MH*NN];

// ---------------- PTX helpers (base ISA only: ldmatrix / mma.sync / cp.async) --
__device__ __forceinline__ uint32_t smem_u32(const void* p) {
    uint32_t a;
    asm("{ .reg .u64 t; cvta.to.shared.u64 t, %1; cvt.u32.u64 %0, t; }"
        : "=r"(a) : "l"(p));
    return a;
}
__device__ __forceinline__ void cp16(uint32_t saddr, const void* g) {
    asm volatile("cp.async.cg.shared.global [%0], [%1], 16;"
                 :: "r"(saddr), "l"(g) : "memory");
}
__device__ __forceinline__ void cp_commit() {
    asm volatile("cp.async.commit_group;" ::: "memory");
}
template<int N_> __device__ __forceinline__ void cp_wait() {
    asm volatile("cp.async.wait_group %0;" :: "n"(N_) : "memory");
}
__device__ __forceinline__ void ldsm4(uint32_t (&r)[4], uint32_t a) {
    asm volatile("ldmatrix.sync.aligned.m8n8.x4.shared.b16 {%0,%1,%2,%3}, [%4];"
                 : "=r"(r[0]), "=r"(r[1]), "=r"(r[2]), "=r"(r[3]) : "r"(a));
}
__device__ __forceinline__ void mma16816(float* c, const uint32_t (&a)[4],
                                         uint32_t b0, uint32_t b1) {
    asm volatile(
        "mma.sync.aligned.m16n8k16.row.col.f32.f16.f16.f32 "
        "{%0,%1,%2,%3}, {%4,%5,%6,%7}, {%8,%9}, {%0,%1,%2,%3};"
        : "+f"(c[0]), "+f"(c[1]), "+f"(c[2]), "+f"(c[3])
        : "r"(a[0]), "r"(a[1]), "r"(a[2]), "r"(a[3]), "r"(b0), "r"(b1));
}
__device__ __forceinline__ void split_f(float x, __half* hp, __half* lp) {
    __half h = __float2half_rn(x);
    *hp = h;
    *lp = __float2half_rn(x - __half2float(h));
}

// ---------------- source resolvers ----------------
__device__ __forceinline__ const float* zc_src(int blk) {
    switch (blk) {
        case 0:  return g_Z0;
        case 1:  return g_Z1f;
        case 2:  return g_Z2f;
        case 3:  return g_Z1b;
        default: return g_Z2b;
    }
}
__device__ __forceinline__ const float* rc_src(int blk) {
    switch (blk) {
        case 0:  return g_RH;
        case 1:  return g_R1f;
        case 2:  return g_R2f;
        case 3:  return g_R1b;
        default: return g_R2b;
    }
}

// ---------------- prologue ----------------
__global__ void zero_init() {
    int idx = blockIdx.x * blockDim.x + threadIdx.x;
    if (idx < 4) g_nz[idx] = 0;
    for (int i = idx; i < MH*NN; i += gridDim.x * blockDim.x) {
        int n  = i & (NN-1);
        int r  = i >> 10;
        int hh = r & (HH-1);
        int b  = r >> 6;
        g_Z0[(b*CIN + 2 + hh)*NN + n] = 0.f;
    }
    for (int i = idx; i < MPAD*NN; i += gridDim.x * blockDim.x) {
        g_Z0hi[i] = __float2half(0.f);
        g_Z0lo[i] = __float2half(0.f);
    }
}

__global__ void mask_detect(const unsigned char* __restrict__ p) {
    int f0 = 0, f1 = 0, f2 = 0, f3 = 0;
    for (int i = blockIdx.x*blockDim.x + threadIdx.x; i < BB*NN*TT;
         i += gridDim.x * blockDim.x) {
        if (p[i]) {
            int c = i & 3;
            if (c == 0) f0 = 1; else if (c == 1) f1 = 1;
            else if (c == 2) f2 = 1; else f3 = 1;
        }
    }
    unsigned b0 = __ballot_sync(0xffffffffu, f0);
    unsigned b1 = __ballot_sync(0xffffffffu, f1);
    unsigned b2 = __ballot_sync(0xffffffffu, f2);
    unsigned b3 = __ballot_sync(0xffffffffu, f3);
    if ((threadIdx.x & 31) == 0) {
        if (b0) atomicOr(&g_nz[0], 1);
        if (b1) atomicOr(&g_nz[1], 1);
        if (b2) atomicOr(&g_nz[2], 1);
        if (b3) atomicOr(&g_nz[3], 1);
    }
}
__global__ void mask_finalize() {
    if ((g_nz[1] | g_nz[2] | g_nz[3]) == 0) g_maskmode = 0;
    else g_maskmode = g_nz[0] ? 1 : 2;
}

__global__ void rowsum_k(const float* __restrict__ adj) {
    int w = blockIdx.x;
    float s = 0.f;
    for (int v = threadIdx.x; v < NN; v += blockDim.x) s += adj[w*NN + v];
    __shared__ float red[256];
    red[threadIdx.x] = s;
    __syncthreads();
    for (int off = 128; off > 0; off >>= 1) {
        if (threadIdx.x < off) red[threadIdx.x] += red[threadIdx.x + off];
        __syncthreads();
    }
    if (threadIdx.x == 0) g_rowinv[w] = 1.f / (red[0] + 1e-8f);
}
__global__ void colsum_k(const float* __restrict__ adj) {
    int w = blockIdx.x * blockDim.x + threadIdx.x;
    if (w >= NN) return;
    float s = 0.f;
    for (int v = 0; v < NN; v++) s += adj[v*NN + w];
    g_colinv[w] = 1.f / (s + 1e-8f);
}
// Bf[w][v] = adj[w][v]*rowinv[w];  Bb[w][v] = adj[v][w]*colinv[w]
__global__ void buildB(const float* __restrict__ adj) {
    for (int i = blockIdx.x*blockDim.x + threadIdx.x; i < NN*NN;
         i += gridDim.x * blockDim.x) {
        int v = i & (NN-1);
        int w = i >> 10;
        g_Bf[i] = adj[i]        * g_rowinv[w];
        g_Bb[i] = adj[v*NN + w] * g_colinv[w];
    }
}

// SIMT SGEMM for one-time support squares: D = S * S (row-major)
__global__ void __launch_bounds__(256)
gemm_simt(int which) {
    const float* S    = which ? g_Bb  : g_Bf;
    const float* Amat = which ? g_Bb  : g_Bf;
    float*       D    = which ? g_Bb2 : g_Bf2;

    const int m0 = blockIdx.y * 64;
    const int n0 = blockIdx.x * 64;
    __shared__ float As[2][16][68];
    __shared__ float Bs[2][16][68];
    const int t  = threadIdx.x;
    const int am = t >> 2;
    const int ak = (t & 3) << 2;
    const int bk = t >> 4;
    const int bn = (t & 15) << 2;
    const int ty = t >> 4;
    const int tx = t & 15;
    const float* Aptr = S + (size_t)(m0 + am)*NN + ak;
    const float* Bptr = Amat + (size_t)bk*NN + n0 + bn;
    float acc[4][4] = {};
    float4 ra = *(const float4*)Aptr;
    float4 rb = *(const float4*)Bptr;
    int buf = 0;
    As[0][ak+0][am] = ra.x; As[0][ak+1][am] = ra.y;
    As[0][ak+2][am] = ra.z; As[0][ak+3][am] = ra.w;
    *(float4*)&Bs[0][bk][bn] = rb;
    __syncthreads();
    #pragma unroll 1
    for (int kc = 0; kc < 64; kc++) {
        if (kc < 63) {
            ra = *(const float4*)(Aptr + (kc+1)*16);
            rb = *(const float4*)(Bptr + (size_t)(kc+1)*16*NN);
        }
        #pragma unroll
        for (int k = 0; k < 16; k++) {
            const float4 av = *(const float4*)&As[buf][k][ty << 2];
            const float4 bv = *(const float4*)&Bs[buf][k][tx << 2];
            acc[0][0] += av.x*bv.x; acc[0][1] += av.x*bv.y;
            acc[0][2] += av.x*bv.z; acc[0][3] += av.x*bv.w;
            acc[1][0] += av.y*bv.x; acc[1][1] += av.y*bv.y;
            acc[1][2] += av.y*bv.z; acc[1][3] += av.y*bv.w;
            acc[2][0] += av.z*bv.x; acc[2][1] += av.z*bv.y;
            acc[2][2] += av.z*bv.z; acc[2][3] += av.z*bv.w;
            acc[3][0] += av.w*bv.x; acc[3][1] += av.w*bv.y;
            acc[3][2] += av.w*bv.z; acc[3][3] += av.w*bv.w;
        }
        if (kc < 63) {
            const int nb = buf ^ 1;
            As[nb][ak+0][am] = ra.x; As[nb][ak+1][am] = ra.y;
            As[nb][ak+2][am] = ra.z; As[nb][ak+3][am] = ra.w;
            *(float4*)&Bs[nb][bk][bn] = rb;
            __syncthreads();
            buf = nb;
        }
    }
    #pragma unroll
    for (int i = 0; i < 4; i++) {
        int m = m0 + (ty << 2) + i;
        *(float4*)(D + (size_t)m*NN + n0 + (tx << 2)) =
            make_float4(acc[i][0], acc[i][1], acc[i][2], acc[i][3]);
    }
}

// convert the 4 supports to fp16 hi/lo, stacked [Bf | Bf2 | Bb | Bb2]
__global__ void convertB() {
    for (int i = blockIdx.x*blockDim.x + threadIdx.x; i < 4*NN*NN;
         i += gridDim.x * blockDim.x) {
        int sect = i >> 20;
        int off  = i & (NN*NN - 1);
        float v;
        if (sect == 0)      v = g_Bf [off];
        else if (sect == 1) v = g_Bf2[off];
        else if (sect == 2) v = g_Bb [off];
        else                v = g_Bb2[off];
        split_f(v, &g_Bcat_hi[i], &g_Bcat_lo[i]);
    }
}

// ---------------- per-step elementwise ----------------
__global__ void phaseA(const float* __restrict__ x, const void* __restrict__ mask,
                       const float* __restrict__ Wout, const float* __restrict__ bout,
                       float* __restrict__ preds, int t) {
    int idx = blockIdx.x * blockDim.x + threadIdx.x;
    if (idx >= MH*NN) return;
    int n  = idx & (NN-1);
    int r  = idx >> 10;
    int hh = r & (HH-1);
    int b  = r >> 6;
    float h = g_Z0[(b*CIN + 2 + hh)*NN + n];
    g_states[(size_t)t*(MH*NN) + idx] = h;
    if (hh == 0) {
        float acc = 0.f;
        #pragma unroll
        for (int k = 0; k < HH; k++)
            acc += Wout[k] * g_Z0[(b*CIN + 2 + k)*NN + n];
        float xh = acc + bout[0];
        int mi = (b*NN + n)*TT + t;
        preds[mi] = xh;
        int mm = g_maskmode;
        float mval;
        if (mm == 0)      mval = ((const int*)mask)[mi]            ? 1.f : 0.f;
        else if (mm == 1) mval = ((const unsigned char*)mask)[mi]  ? 1.f : 0.f;
        else              mval = (((const float*)mask)[mi] != 0.f) ? 1.f : 0.f;
        float xin = (mval != 0.f) ? x[mi] : xh;
        int r0 = (b*CIN + 0)*NN + n;
        int r1 = (b*CIN + 1)*NN + n;
        g_Z0[r0] = xin;
        g_Z0[r1] = mval;
        split_f(xin,  &g_Z0hi[r0], &g_Z0lo[r0]);
        split_f(mval, &g_Z0hi[r1], &g_Z0lo[r1]);
    }
}

// ---------------- HMMA diffusion GEMM (mma.sync, fp16 split x3, f32 acc) ------
// D[m][n] = sum_k A[m][k] * Bcat[sect*1024 + n][k]
// mode 0: A = Z0hi/lo (640 rows), outputs Z1f/Z2f/Z1b/Z2b
// mode 1: A = RHhi/lo (512 rows), outputs R1f/R2f/R1b/R2b
#define KC        64
#define ROWH      72                 // halves per smem row (64 + 8 pad)
#define TILE_HALF (128*ROWH)         // 9216 halves
#define STG_HALF  (4*TILE_HALF)      // 4 tiles per stage
#define GEMM_SMEM (2*STG_HALF*2)     // bytes = 147456

__global__ void __launch_bounds__(256, 1)
gemm_hmma(int mode) {
    extern __shared__ __align__(16) __half sh[];
    const int tid  = threadIdx.x;
    const int wid  = tid >> 5;
    const int lane = tid & 31;
    const int nt   = blockIdx.x;        // 0..31
    const int mt   = blockIdx.y;
    const int sect = nt >> 3;
    const int nloc = (nt & 7) * 128;
    const int mrow0 = mt * 128;

    const __half* Ahi = mode ? g_RHhi : g_Z0hi;
    const __half* Alo = mode ? g_RHlo : g_Z0lo;
    const __half* Bhi = g_Bcat_hi + ((size_t)sect << 20);
    const __half* Blo = g_Bcat_lo + ((size_t)sect << 20);
    float* Dout;
    if (mode == 0)
        Dout = (sect==0) ? g_Z1f : (sect==1) ? g_Z2f : (sect==2) ? g_Z1b : g_Z2b;
    else
        Dout = (sect==0) ? g_R1f : (sect==1) ? g_R2f : (sect==2) ? g_R1b : g_R2b;

    const int wm = wid >> 2;      // 0..1  (64-row band)
    const int wn = wid & 3;       // 0..3  (32-col band)
    const uint32_t sbase = smem_u32(sh);

    // ldmatrix lane addressing for a 16x16 b16 block (4x 8x8 matrices)
    const uint32_t lrow = (lane & 7) | (((lane >> 3) & 1) << 3);
    const uint32_t lcol = (uint32_t)(lane >> 4) << 3;

    float acc[4][4][4] = {};

    // ---- prefetch lambda: one k-chunk (all 4 tiles) via cp.async ----
    auto prefetch = [&](int kc, int stg) {
        const int r  = (tid >> 3);        // 0..31
        const int c  = tid & 7;           // 16B unit in 128B row
        #pragma unroll
        for (int t4 = 0; t4 < 4; t4++) {
            const __half* src = (t4 == 0) ? Ahi : (t4 == 1) ? Alo
                              : (t4 == 2) ? Bhi : Blo;
            const int grow0 = (t4 < 2) ? mrow0 : nloc;
            #pragma unroll
            for (int j = 0; j < 4; j++) {
                int rr = j*32 + r;
                const __half* g = src + (size_t)(grow0 + rr)*NN + kc*KC + c*8;
                uint32_t sa = sbase +
                    (uint32_t)(((stg*4 + t4)*128 + rr)*ROWH + c*8)*2;
                cp16(sa, g);
            }
        }
    };

    prefetch(0, 0);
    cp_commit();

    #pragma unroll 1
    for (int kc = 0; kc < NN/KC; kc++) {
        if (kc < NN/KC - 1) {
            prefetch(kc + 1, (kc + 1) & 1);
            cp_commit();
            cp_wait<1>();
        } else {
            cp_wait<0>();
        }
        __syncthreads();
        const uint32_t stoff = sbase + (uint32_t)((kc & 1)*STG_HALF)*2;

        #pragma unroll
        for (int ks = 0; ks < 4; ks++) {
            uint32_t ah[4][4], al[4][4], bh[2][4], bl[2][4];
            #pragma unroll
            for (int mi = 0; mi < 4; mi++) {
                uint32_t roff = (wm*64 + mi*16 + lrow)*ROWH + ks*16 + lcol;
                ldsm4(ah[mi], stoff + (0*TILE_HALF + roff)*2);
                ldsm4(al[mi], stoff + (1*TILE_HALF + roff)*2);
            }
            #pragma unroll
            for (int pj = 0; pj < 2; pj++) {
                uint32_t roff = (wn*32 + pj*16 + lrow)*ROWH + ks*16 + lcol;
                ldsm4(bh[pj], stoff + (2*TILE_HALF + roff)*2);
                ldsm4(bl[pj], stoff + (3*TILE_HALF + roff)*2);
            }
            #pragma unroll
            for (int mi = 0; mi < 4; mi++) {
                #pragma unroll
                for (int nj = 0; nj < 4; nj++) {
                    uint32_t b0h = bh[nj>>1][nj&1], b1h = bh[nj>>1][(nj&1)+2];
                    uint32_t b0l = bl[nj>>1][nj&1], b1l = bl[nj>>1][(nj&1)+2];
                    mma16816(acc[mi][nj], ah[mi], b0h, b1h);
                    mma16816(acc[mi][nj], al[mi], b0h, b1h);
                    mma16816(acc[mi][nj], ah[mi], b0l, b1l);
                }
            }
        }
        __syncthreads();
    }

    // ---- epilogue: direct f32 stores ----
    #pragma unroll
    for (int mi = 0; mi < 4; mi++) {
        int m = mrow0 + wm*64 + mi*16 + (lane >> 2);
        #pragma unroll
        for (int nj = 0; nj < 4; nj++) {
            int n = nloc + wn*32 + nj*8 + (lane & 3)*2;
            float2 v0 = make_float2(acc[mi][nj][0], acc[mi][nj][1]);
            float2 v1 = make_float2(acc[mi][nj][2], acc[mi][nj][3]);
            *(float2*)(Dout + (size_t)m*NN + n)       = v0;
            *(float2*)(Dout + (size_t)(m + 8)*NN + n) = v1;
        }
    }
}

// ---------------- r/u gates ----------------
__global__ void __launch_bounds__(256)
gates_ru(const float* __restrict__ Wr, const float* __restrict__ br,
         const float* __restrict__ Wu, const float* __restrict__ bu) {
    const int b  = blockIdx.y;
    const int n0 = blockIdx.x * 64;
    __shared__ float Ws[8][128];
    __shared__ float Zs[8][64];
    const int t  = threadIdx.x;
    const int ty = t >> 4;
    const int tx = t & 15;
    float acc[8][4] = {};
    for (int c0 = 0; c0 < KTOT; c0 += 8) {
        #pragma unroll
        for (int i = 0; i < 4; i++) {
            int idx = t + i*256;
            int kk = idx >> 7, o = idx & 127;
            int c = c0 + kk;
            float w = 0.f;
            if (c < KTOT) w = (o < 64) ? Wr[o*KTOT + c] : Wu[(o-64)*KTOT + c];
            Ws[kk][o] = w;
        }
        #pragma unroll
        for (int i = 0; i < 2; i++) {
            int idx = t + i*256;
            int kk = idx >> 6, nn2 = idx & 63;
            int c = c0 + kk;
            float z = 0.f;
            if (c < KTOT) {
                int blk = c / 66, cc = c - blk*66;
                z = zc_src(blk)[(b*CIN + cc)*NN + n0 + nn2];
            }
            Zs[kk][nn2] = z;
        }
        __syncthreads();
        #pragma unroll
        for (int kk = 0; kk < 8; kk++) {
            float4 w0 = *(const float4*)&Ws[kk][ty*8];
            float4 w1 = *(const float4*)&Ws[kk][ty*8 + 4];
            float4 zz = *(const float4*)&Zs[kk][tx*4];
            float wv[8] = {w0.x,w0.y,w0.z,w0.w,w1.x,w1.y,w1.z,w1.w};
            float zv[4] = {zz.x,zz.y,zz.z,zz.w};
            #pragma unroll
            for (int i = 0; i < 8; i++)
                #pragma unroll
                for (int j = 0; j < 4; j++)
                    acc[i][j] += wv[i]*zv[j];
        }
        __syncthreads();
    }
    #pragma unroll
    for (int i = 0; i < 8; i++) {
        int o = ty*8 + i;
        float bias = (o < 64) ? br[o] : bu[o-64];
        #pragma unroll
        for (int j = 0; j < 4; j++) {
            int n = n0 + tx*4 + j;
            float p = acc[i][j] + bias;
            float s = 1.f / (1.f + expf(-p));
            if (o < 64) {
                int ri = (b*HH + o)*NN + n;
                float rh = s * g_Z0[(b*CIN + 2 + o)*NN + n];
                g_RH[ri] = rh;
                split_f(rh, &g_RHhi[ri], &g_RHlo[ri]);
            } else {
                g_U[(b*HH + (o-64))*NN + n] = s;
            }
        }
    }
}

// ---------------- c gate + h update ----------------
__global__ void __launch_bounds__(256)
gate_c(const float* __restrict__ Wc, const float* __restrict__ bc) {
    const int b  = blockIdx.y;
    const int n0 = blockIdx.x * 64;
    __shared__ float Ws[8][64];
    __shared__ float Zs[8][64];
    const int t  = threadIdx.x;
    const int ty = t >> 4;
    const int tx = t & 15;
    float acc[4][4] = {};
    for (int c0 = 0; c0 < KTOT; c0 += 8) {
        #pragma unroll
        for (int i = 0; i < 2; i++) {
            int idx = t + i*256;
            int kk = idx >> 6, o = idx & 63;
            int c = c0 + kk;
            Ws[kk][o] = (c < KTOT) ? Wc[o*KTOT + c] : 0.f;
        }
        #pragma unroll
        for (int i = 0; i < 2; i++) {
            int idx = t + i*256;
            int kk = idx >> 6, nn2 = idx & 63;
            int c = c0 + kk;
            float z = 0.f;
            if (c < KTOT) {
                int blk = c / 66, cc = c - blk*66;
                if (cc < 2) z = zc_src(blk)[(b*CIN + cc)*NN + n0 + nn2];
                else        z = rc_src(blk)[(b*HH + cc - 2)*NN + n0 + nn2];
            }
            Zs[kk][nn2] = z;
        }
        __syncthreads();
        #pragma unroll
        for (int kk = 0; kk < 8; kk++) {
            float4 w4 = *(const float4*)&Ws[kk][ty*4];
            float4 z4 = *(const float4*)&Zs[kk][tx*4];
            float wv[4] = {w4.x,w4.y,w4.z,w4.w};
            float zv[4] = {z4.x,z4.y,z4.z,z4.w};
            #pragma unroll
            for (int i = 0; i < 4; i++)
                #pragma unroll
                for (int j = 0; j < 4; j++)
                    acc[i][j] += wv[i]*zv[j];
        }
        __syncthreads();
    }
    #pragma unroll
    for (int i = 0; i < 4; i++) {
        int o = ty*4 + i;
        float bias = bc[o];
        #pragma unroll
        for (int j = 0; j < 4; j++) {
            int n = n0 + tx*4 + j;
            float cv = tanhf(acc[i][j] + bias);
            int zi = (b*CIN + 2 + o)*NN + n;
            float hold = g_Z0[zi];
            float u    = g_U[(b*HH + o)*NN + n];
            float hnew = u*hold + (1.f - u)*cv;
            g_Z0[zi] = hnew;
            split_f(hnew, &g_Z0hi[zi], &g_Z0lo[zi]);
        }
    }
}

// ---------------- epilogue transpose ----------------
__global__ void transpose_states(float* __restrict__ dst) {
    __shared__ float tile[32][33];
    const int m0 = blockIdx.x * 32;
    const int t0 = blockIdx.y * 32;
    const int tx = threadIdx.x;
    const int ty = threadIdx.y;
    #pragma unroll
    for (int j = 0; j < 4; j++) {
        int tt = t0 + ty + j*8;
        tile[ty + j*8][tx] = g_states[(size_t)tt*(MH*NN) + m0 + tx];
    }
    __syncthreads();
    #pragma unroll
    for (int j = 0; j < 4; j++) {
        int mm = m0 + ty + j*8;
        dst[(size_t)mm*TT + t0 + tx] = tile[tx][ty + j*8];
    }
}

// ---------------- host driver ----------------
extern "C" void kernel_launch(void* const* d_in, const int* in_sizes, int n_in,
                              void* d_out, int out_size) {
    const float* x    = (const float*)d_in[0];
    const void*  mask = d_in[1];
    const float* adj  = (const float*)d_in[2];
    const float* Wr   = (const float*)d_in[3];
    const float* br   = (const float*)d_in[4];
    const float* Wu   = (const float*)d_in[5];
    const float* bu   = (const float*)d_in[6];
    const float* Wc   = (const float*)d_in[7];
    const float* bc   = (const float*)d_in[8];
    const float* Wout = (const float*)d_in[9];
    const float* bout = (const float*)d_in[10];

    float* preds  = (float*)d_out;
    float* states = preds + (size_t)BB*NN*TT;

    cudaFuncSetAttribute(gemm_hmma, cudaFuncAttributeMaxDynamicSharedMemorySize,
                         GEMM_SMEM);

    zero_init<<<512, 256>>>();
    mask_detect<<<64, 256>>>((const unsigned char*)mask);
    mask_finalize<<<1, 1>>>();
    rowsum_k<<<NN, 256>>>(adj);
    colsum_k<<<NN/256, 256>>>(adj);
    buildB<<<2048, 256>>>(adj);
    gemm_simt<<<dim3(16, 16), 256>>>(0);   // Bf2 = Bf*Bf
    gemm_simt<<<dim3(16, 16), 256>>>(1);   // Bb2 = Bb*Bb
    convertB<<<2048, 256>>>();

    dim3 gBC(32, MPAD/128);   // 32 x 5
    dim3 gEF(32, MH/128);     // 32 x 4
    dim3 gGate(16, BB);

    for (int t = 0; t < TT; t++) {
        phaseA<<<(MH*NN)/256, 256>>>(x, mask, Wout, bout, preds, t);
        gemm_hmma<<<gBC, 256, GEMM_SMEM>>>(0);
        gates_ru<<<gGate, 256>>>(Wr, br, Wu, bu);
        gemm_hmma<<<gEF, 256, GEMM_SMEM>>>(1);
        gate_c<<<gGate, 256>>>(Wc, bc);
    }

    transpose_states<<<dim3((MH*NN)/32, TT/32), dim3(32, 8)>>>(states);
}